// round 1
// baseline (speedup 1.0000x reference)
#include <cuda_runtime.h>
#include <cstdint>

// Problem shape (fixed by reference)
constexpr int B = 16, N = 8, M = 1024, F = 512;
constexpr int F4 = F / 4;          // 128 float4 columns
constexpr int M_CHUNK = 64;        // m-rows per block
constexpr int M_CHUNKS = M / M_CHUNK;  // 16
constexpr float LOG2E = 1.4426950408889634f;

// Flag: 1 if mask is stored as int64 (odd 32-bit words all zero), else int32.
__device__ int g_mask_is64;

// ---------------------------------------------------------------------------
// Detect mask element width. Values are in [0,13), so if the source is int64
// (little-endian), every odd 32-bit word is exactly 0. For int32 data the OR
// over 256 odd words is nonzero with probability 1 - (1/13)^256.
// ---------------------------------------------------------------------------
__global__ void detect_mask_width_kernel(const int* __restrict__ mask32) {
    unsigned acc = 0;
    // 256 odd words, 32 lanes -> 8 words per lane
    for (int i = threadIdx.x; i < 256; i += 32) {
        acc |= (unsigned)mask32[2 * i + 1];
    }
    // warp OR-reduce
    #pragma unroll
    for (int off = 16; off > 0; off >>= 1)
        acc |= __shfl_xor_sync(0xFFFFFFFFu, acc, off);
    if (threadIdx.x == 0)
        g_mask_is64 = (acc == 0u) ? 1 : 0;
}

// ---------------------------------------------------------------------------
// Main kernel: one block = (b, n, m_chunk); 128 threads = one float4 column
// each. Params are gathered once per thread into registers, then 64 m-rows
// are streamed with coalesced float4 loads/stores.
// tanh(x) = 1 - 2/(exp(2x)+1)  ->  out = p - q * rcp(ex2(z*c1 + c0))
//   c1 = 2*e3*log2(e), c0 = -2*e2*e3*log2(e), p = e0+e1, q = 2*e1
// ---------------------------------------------------------------------------
__device__ __forceinline__ float ex2_approx(float x) {
    float r;
    asm("ex2.approx.f32 %0, %1;" : "=f"(r) : "f"(x));
    return r;
}
__device__ __forceinline__ float rcp_approx(float x) {
    float r;
    asm("rcp.approx.f32 %0, %1;" : "=f"(r) : "f"(x));
    return r;
}

__global__ __launch_bounds__(F4, 8)
void tanh_rt_kernel(const float4* __restrict__ z,
                    const int* __restrict__ mask32,
                    const float4* __restrict__ eta,   // [13] of (e0,e1,e2,e3)
                    float4* __restrict__ out) {
    const int f4  = threadIdx.x;           // 0..127
    const int blk = blockIdx.x;
    const int mc  = blk % M_CHUNKS;
    const int bn  = blk / M_CHUNKS;        // 0..B*N-1
    const int n   = bn % N;
    const int b   = bn / N;

    const int is64 = g_mask_is64;          // uniform branch, cached

    float c1[4], c0[4], p[4], q[4];
    #pragma unroll
    for (int j = 0; j < 4; j++) {
        const int f = f4 * 4 + j;
        const int pos = b * F + f;
        const int midx = is64 ? mask32[2 * pos] : mask32[pos];
        const float4 e = __ldg(&eta[midx]);
        const float t1 = 2.0f * e.w * LOG2E;       // 2*e3*log2e
        c1[j] = t1;
        c0[j] = -e.z * t1;                         // -2*e2*e3*log2e
        p[j]  = e.x + e.y;                         // e0 + e1
        q[j]  = 2.0f * e.y;                        // 2*e1
    }

    size_t base = ((size_t)(b * N + n) * M + (size_t)mc * M_CHUNK) * F4 + f4;

    #pragma unroll 4
    for (int m = 0; m < M_CHUNK; m++) {
        const size_t idx = base + (size_t)m * F4;
        float4 zv = z[idx];
        float4 o;
        {
            float t = ex2_approx(fmaf(zv.x, c1[0], c0[0]));
            o.x = fmaf(-q[0], rcp_approx(t + 1.0f), p[0]);
        }
        {
            float t = ex2_approx(fmaf(zv.y, c1[1], c0[1]));
            o.y = fmaf(-q[1], rcp_approx(t + 1.0f), p[1]);
        }
        {
            float t = ex2_approx(fmaf(zv.z, c1[2], c0[2]));
            o.z = fmaf(-q[2], rcp_approx(t + 1.0f), p[2]);
        }
        {
            float t = ex2_approx(fmaf(zv.w, c1[3], c0[3]));
            o.w = fmaf(-q[3], rcp_approx(t + 1.0f), p[3]);
        }
        out[idx] = o;
    }
}

extern "C" void kernel_launch(void* const* d_in, const int* in_sizes, int n_in,
                              void* d_out, int out_size) {
    const float4* z      = (const float4*)d_in[0];
    const int*    mask32 = (const int*)d_in[1];      // int32 or int64, detected
    const float4* eta    = (const float4*)d_in[2];   // [13,4] fp32
    float4*       out    = (float4*)d_out;

    detect_mask_width_kernel<<<1, 32>>>(mask32);
    tanh_rt_kernel<<<B * N * M_CHUNKS, F4>>>(z, mask32, eta, out);
}

// round 2
// speedup vs baseline: 1.1092x; 1.1092x over previous
#include <cuda_runtime.h>
#include <cstdint>

// Problem shape (fixed by reference)
constexpr int B = 16, N = 8, M = 1024, F = 512;
constexpr int F4 = F / 4;              // 128 float4 columns
constexpr int M_CHUNK = 16;            // m-rows per block (fine-grained for wave balance)
constexpr int M_CHUNKS = M / M_CHUNK;  // 64
constexpr float LOG2E = 1.4426950408889634f;

__device__ __forceinline__ float ex2_approx(float x) {
    float r;
    asm("ex2.approx.f32 %0, %1;" : "=f"(r) : "f"(x));
    return r;
}
__device__ __forceinline__ float rcp_approx(float x) {
    float r;
    asm("rcp.approx.f32 %0, %1;" : "=f"(r) : "f"(x));
    return r;
}

// ---------------------------------------------------------------------------
// One block = (b, n, m_chunk); 128 threads = one float4 f-column each.
//
// Mask dtype detection is done IN-BLOCK (no separate launch): mask values are
// in [0,13), so if the source is little-endian int64 every odd 32-bit word is
// exactly 0; for int32 data the OR over 256 odd words is nonzero with
// probability 1-(1/13)^256. The 256 words live in L2 after the first blocks
// touch them, so this costs ~nothing.
//
// tanh(x) = 1 - 2/(exp(2x)+1)  ->  out = p - q * rcp(ex2(z*c1 + c0) + 1)
//   c1 = 2*e3*log2e, c0 = -2*e2*e3*log2e, p = e0+e1, q = 2*e1
// ---------------------------------------------------------------------------
__global__ __launch_bounds__(F4, 8)
void tanh_rt_kernel(const float4* __restrict__ z,
                    const int* __restrict__ mask32,
                    const float4* __restrict__ eta,   // [13] of (e0,e1,e2,e3)
                    float4* __restrict__ out) {
    const int f4  = threadIdx.x;           // 0..127
    const int blk = blockIdx.x;
    const int mc  = blk % M_CHUNKS;
    const int bn  = blk / M_CHUNKS;        // 0..B*N-1
    const int n   = bn % N;
    const int b   = bn / N;

    // --- in-block mask width detection (block-uniform result) ---
    unsigned acc = (unsigned)mask32[2 * f4 + 1] | (unsigned)mask32[2 * (f4 + 128) + 1];
    const int is64 = !__syncthreads_or((int)acc);

    // --- gather per-f params once into registers ---
    float c1[4], c0[4], p[4], q[4];
    #pragma unroll
    for (int j = 0; j < 4; j++) {
        const int f = f4 * 4 + j;
        const int pos = b * F + f;
        const int midx = is64 ? mask32[2 * pos] : mask32[pos];
        const float4 e = __ldg(&eta[midx]);
        const float t1 = 2.0f * e.w * LOG2E;       // 2*e3*log2e
        c1[j] = t1;
        c0[j] = -e.z * t1;                         // -2*e2*e3*log2e
        p[j]  = e.x + e.y;                         // e0 + e1
        q[j]  = 2.0f * e.y;                        // 2*e1
    }

    size_t base = ((size_t)(b * N + n) * M + (size_t)mc * M_CHUNK) * F4 + f4;

    // --- stream M_CHUNK rows: batch 2 float4 loads, compute, store ---
    #pragma unroll 4
    for (int m = 0; m < M_CHUNK; m += 2) {
        const size_t i0 = base + (size_t)m * F4;
        const size_t i1 = i0 + F4;
        float4 z0 = z[i0];
        float4 z1 = z[i1];
        float4 o0, o1;

        o0.x = fmaf(-q[0], rcp_approx(ex2_approx(fmaf(z0.x, c1[0], c0[0])) + 1.0f), p[0]);
        o0.y = fmaf(-q[1], rcp_approx(ex2_approx(fmaf(z0.y, c1[1], c0[1])) + 1.0f), p[1]);
        o0.z = fmaf(-q[2], rcp_approx(ex2_approx(fmaf(z0.z, c1[2], c0[2])) + 1.0f), p[2]);
        o0.w = fmaf(-q[3], rcp_approx(ex2_approx(fmaf(z0.w, c1[3], c0[3])) + 1.0f), p[3]);

        o1.x = fmaf(-q[0], rcp_approx(ex2_approx(fmaf(z1.x, c1[0], c0[0])) + 1.0f), p[0]);
        o1.y = fmaf(-q[1], rcp_approx(ex2_approx(fmaf(z1.y, c1[1], c0[1])) + 1.0f), p[1]);
        o1.z = fmaf(-q[2], rcp_approx(ex2_approx(fmaf(z1.z, c1[2], c0[2])) + 1.0f), p[2]);
        o1.w = fmaf(-q[3], rcp_approx(ex2_approx(fmaf(z1.w, c1[3], c0[3])) + 1.0f), p[3]);

        out[i0] = o0;
        out[i1] = o1;
    }
}

extern "C" void kernel_launch(void* const* d_in, const int* in_sizes, int n_in,
                              void* d_out, int out_size) {
    const float4* z      = (const float4*)d_in[0];
    const int*    mask32 = (const int*)d_in[1];      // int32 or int64, detected in-kernel
    const float4* eta    = (const float4*)d_in[2];   // [13,4] fp32
    float4*       out    = (float4*)d_out;

    tanh_rt_kernel<<<B * N * M_CHUNKS, F4>>>(z, mask32, eta, out);
}